// round 1
// baseline (speedup 1.0000x reference)
#include <cuda_runtime.h>
#include <math.h>
#include <stdint.h>

// Problem constants
#define Nn   2048
#define Cc   1024
#define Hh   8
#define HD   128
#define SCALE_F 25.0f
#define SIM_THRESH 0.75f

// ---------------- scratch (device globals; no allocation allowed) ----------------
__device__ float g_qkv[Nn * 3 * Cc];            // [n][3C] raw qkv GEMM output
__device__ float g_q[Hh * Nn * HD];             // qn * SCALE, head-major [h][n][d]
__device__ float g_k[Hh * Nn * HD];             // kn, head-major
__device__ float g_vflat[Nn * Cc];              // raw v, flat [n][h*128+d]
__device__ float g_vnflat[Nn * Cc];             // per-head-normalized v, flat
__device__ float g_vT[Hh * HD * Nn];            // raw v transposed, [h][d][n]
__device__ float g_sim[Nn * Nn];                // sum_h vn.vn (before /8)
__device__ float g_attn[(size_t)Hh * Nn * Nn];  // logits -> softmaxed attn per head

// ---------------- generic NT SGEMM: C[M,N] = A[M,K] @ B[N,K]^T ----------------
// BM=BN=128, BK=16, 256 threads, 8x8 microtile. Requires M%128==0, N%128==0, K%16==0.
#define BM 128
#define BN 128
#define BK 16

__global__ __launch_bounds__(256) void sgemm_nt(
    const float* __restrict__ A, const float* __restrict__ B, float* __restrict__ C,
    int M, int N, int K, int lda, int ldb, int ldc,
    long long strideA, long long strideB, long long strideC)
{
    A += (long long)blockIdx.z * strideA;
    B += (long long)blockIdx.z * strideB;
    C += (long long)blockIdx.z * strideC;

    const int bm = blockIdx.y * BM;
    const int bn = blockIdx.x * BN;

    __shared__ float As[BK][BM];
    __shared__ float Bs[BK][BN];

    const int tid = threadIdx.x;
    const int tx = tid & 15;   // N direction
    const int ty = tid >> 4;   // M direction

    float acc[8][8];
    #pragma unroll
    for (int i = 0; i < 8; i++)
        #pragma unroll
        for (int j = 0; j < 8; j++) acc[i][j] = 0.f;

    for (int k0 = 0; k0 < K; k0 += BK) {
        // load A tile: 128x16 = 512 float4 loads, 2 per thread
        #pragma unroll
        for (int t = 0; t < 2; t++) {
            int idx = tid + t * 256;
            int row = idx >> 2;
            int kc  = (idx & 3) * 4;
            float4 v = *reinterpret_cast<const float4*>(&A[(long long)(bm + row) * lda + k0 + kc]);
            As[kc + 0][row] = v.x; As[kc + 1][row] = v.y;
            As[kc + 2][row] = v.z; As[kc + 3][row] = v.w;
        }
        #pragma unroll
        for (int t = 0; t < 2; t++) {
            int idx = tid + t * 256;
            int row = idx >> 2;
            int kc  = (idx & 3) * 4;
            float4 v = *reinterpret_cast<const float4*>(&B[(long long)(bn + row) * ldb + k0 + kc]);
            Bs[kc + 0][row] = v.x; Bs[kc + 1][row] = v.y;
            Bs[kc + 2][row] = v.z; Bs[kc + 3][row] = v.w;
        }
        __syncthreads();

        #pragma unroll
        for (int k = 0; k < BK; k++) {
            float a[8], b[8];
            *reinterpret_cast<float4*>(&a[0]) = *reinterpret_cast<const float4*>(&As[k][ty * 8]);
            *reinterpret_cast<float4*>(&a[4]) = *reinterpret_cast<const float4*>(&As[k][ty * 8 + 4]);
            *reinterpret_cast<float4*>(&b[0]) = *reinterpret_cast<const float4*>(&Bs[k][tx * 8]);
            *reinterpret_cast<float4*>(&b[4]) = *reinterpret_cast<const float4*>(&Bs[k][tx * 8 + 4]);
            #pragma unroll
            for (int i = 0; i < 8; i++)
                #pragma unroll
                for (int j = 0; j < 8; j++)
                    acc[i][j] += a[i] * b[j];
        }
        __syncthreads();
    }

    #pragma unroll
    for (int i = 0; i < 8; i++) {
        long long row = bm + ty * 8 + i;
        #pragma unroll
        for (int j = 0; j < 8; j += 4) {
            float4 v = make_float4(acc[i][j], acc[i][j + 1], acc[i][j + 2], acc[i][j + 3]);
            *reinterpret_cast<float4*>(&C[row * ldc + bn + tx * 8 + j]) = v;
        }
    }
}

// ---------------- normalize: split qkv, L2-normalize per head, build layouts ----------------
// grid 2048 (one block per n), 256 threads (warp w = head w)
__global__ __launch_bounds__(256) void normalize_kernel()
{
    const int n = blockIdx.x;
    const int w = threadIdx.x >> 5;   // head
    const int lane = threadIdx.x & 31;
    const float* base = g_qkv + (long long)n * (3 * Cc);

    float qv[4], kv[4], vv[4];
    #pragma unroll
    for (int r = 0; r < 4; r++) {
        int d = lane + 32 * r;
        qv[r] = base[0 * Cc + w * HD + d];
        kv[r] = base[1 * Cc + w * HD + d];
        vv[r] = base[2 * Cc + w * HD + d];
    }
    float sq = 0.f, sk = 0.f, sv = 0.f;
    #pragma unroll
    for (int r = 0; r < 4; r++) { sq += qv[r] * qv[r]; sk += kv[r] * kv[r]; sv += vv[r] * vv[r]; }
    #pragma unroll
    for (int o = 16; o > 0; o >>= 1) {
        sq += __shfl_xor_sync(0xffffffffu, sq, o);
        sk += __shfl_xor_sync(0xffffffffu, sk, o);
        sv += __shfl_xor_sync(0xffffffffu, sv, o);
    }
    const float iq = SCALE_F / sqrtf(sq);
    const float ik = 1.0f / sqrtf(sk);
    const float iv = 1.0f / sqrtf(sv);

    #pragma unroll
    for (int r = 0; r < 4; r++) {
        int d = lane + 32 * r;
        g_q[(long long)w * Nn * HD + (long long)n * HD + d] = qv[r] * iq;
        g_k[(long long)w * Nn * HD + (long long)n * HD + d] = kv[r] * ik;
        g_vflat[(long long)n * Cc + w * HD + d]  = vv[r];
        g_vnflat[(long long)n * Cc + w * HD + d] = vv[r] * iv;
        g_vT[(long long)w * HD * Nn + (long long)d * Nn + n] = vv[r];
    }
}

// ---------------- block reduction helpers ----------------
__device__ __forceinline__ float blockMax(float v, float* sh)
{
    int tid = threadIdx.x;
    #pragma unroll
    for (int o = 16; o > 0; o >>= 1) v = fmaxf(v, __shfl_xor_sync(0xffffffffu, v, o));
    __syncthreads();
    if ((tid & 31) == 0) sh[tid >> 5] = v;
    __syncthreads();
    if (tid == 0) { float r = sh[0]; for (int i = 1; i < 8; i++) r = fmaxf(r, sh[i]); sh[8] = r; }
    __syncthreads();
    return sh[8];
}

__device__ __forceinline__ float blockSum(float v, float* sh)
{
    int tid = threadIdx.x;
    #pragma unroll
    for (int o = 16; o > 0; o >>= 1) v += __shfl_xor_sync(0xffffffffu, v, o);
    __syncthreads();
    if ((tid & 31) == 0) sh[tid >> 5] = v;
    __syncthreads();
    if (tid == 0) { float r = sh[0]; for (int i = 1; i < 8; i++) r += sh[i]; sh[8] = r; }
    __syncthreads();
    return sh[8];
}

// ---------------- per-row masked-scaled softmax over logits (in place) ----------------
// grid (2048 rows, 8 heads), 256 threads. SCALE is already folded into qn.
// logit = raw * cls[j] * (cls[j] > cls[i]-0.1 ? 1 : 0); masked entries become 0 (not -inf).
__global__ __launch_bounds__(256) void softmax_kernel(const float* __restrict__ cls)
{
    const int i = blockIdx.x;
    const int h = blockIdx.y;
    const int tid = threadIdx.x;
    float* row = g_attn + (size_t)h * Nn * Nn + (size_t)i * Nn;
    const float thr = cls[i] - 0.1f;

    __shared__ float sh[16];
    float lv[8];
    float m = -1e30f;
    #pragma unroll
    for (int r = 0; r < 8; r++) {
        int j = tid + 256 * r;
        float cj = cls[j];
        float l = (cj > thr) ? row[j] * cj : 0.f;
        lv[r] = l;
        m = fmaxf(m, l);
    }
    m = blockMax(m, sh);
    float s = 0.f;
    #pragma unroll
    for (int r = 0; r < 8; r++) { lv[r] = expf(lv[r] - m); s += lv[r]; }
    s = blockSum(s, sh);
    const float iz = 1.0f / s;
    #pragma unroll
    for (int r = 0; r < 8; r++) row[tid + 256 * r] = lv[r] * iz;
}

// ---------------- copy raw v into second half of x_out ----------------
__global__ __launch_bounds__(256) void copy_v_kernel(float* __restrict__ out)
{
    int idx = blockIdx.x * blockDim.x + threadIdx.x;  // over 2048*1024/4 float4
    if (idx >= Nn * Cc / 4) return;
    int n = idx / (Cc / 4);
    int c4 = idx % (Cc / 4);
    float4 v = reinterpret_cast<const float4*>(g_vflat)[(size_t)n * (Cc / 4) + c4];
    reinterpret_cast<float4*>(out)[(size_t)n * (2 * Cc / 4) + (Cc / 4) + c4] = v;
}

// ---------------- sim_round2: head-avg attn -> softmax -> mask(sim>0.75) -> renorm ----------------
__global__ __launch_bounds__(256) void simround2_kernel(float* __restrict__ out_sim)
{
    const int i = blockIdx.x;
    const int tid = threadIdx.x;
    __shared__ float sh[16];

    float s[8];
    #pragma unroll
    for (int r = 0; r < 8; r++) {
        int j = tid + 256 * r;
        float acc = 0.f;
        #pragma unroll
        for (int h = 0; h < 8; h++)
            acc += g_attn[(size_t)h * Nn * Nn + (size_t)i * Nn + j];
        s[r] = acc * 0.125f;
    }
    float m = -1e30f;
    #pragma unroll
    for (int r = 0; r < 8; r++) m = fmaxf(m, s[r]);
    m = blockMax(m, sh);
    float z = 0.f;
    #pragma unroll
    for (int r = 0; r < 8; r++) { s[r] = expf(s[r] - m); z += s[r]; }
    z = blockSum(z, sh);
    const float iz = 1.0f / z;

    float msum = 0.f;
    #pragma unroll
    for (int r = 0; r < 8; r++) {
        int j = tid + 256 * r;
        float mk = (g_sim[(size_t)i * Nn + j] * 0.125f > SIM_THRESH) ? 1.f : 0.f;
        s[r] = mk * s[r] * iz;
        msum += s[r];
    }
    msum = blockSum(msum, sh);
    const float inv = 1.0f / msum;
    #pragma unroll
    for (int r = 0; r < 8; r++)
        out_sim[(size_t)i * Nn + tid + 256 * r] = s[r] * inv;
}

// ---------------- host launcher ----------------
extern "C" void kernel_launch(void* const* d_in, const int* in_sizes, int n_in,
                              void* d_out, int out_size)
{
    const float* x   = (const float*)d_in[0];  // [2048,1024]
    const float* cls = (const float*)d_in[1];  // [2048]
    const float* W   = (const float*)d_in[3];  // [3072,1024]
    float* out = (float*)d_out;                // x_out [2048,2048] then sim [2048,2048]

    float *p_qkv, *p_q, *p_k, *p_vnflat, *p_vT, *p_sim, *p_attn;
    cudaGetSymbolAddress((void**)&p_qkv, g_qkv);
    cudaGetSymbolAddress((void**)&p_q, g_q);
    cudaGetSymbolAddress((void**)&p_k, g_k);
    cudaGetSymbolAddress((void**)&p_vnflat, g_vnflat);
    cudaGetSymbolAddress((void**)&p_vT, g_vT);
    cudaGetSymbolAddress((void**)&p_sim, g_sim);
    cudaGetSymbolAddress((void**)&p_attn, g_attn);

    // 1. qkv = x @ W^T : [2048,3072]
    sgemm_nt<<<dim3(3 * Cc / BN, Nn / BM, 1), 256>>>(
        x, W, p_qkv, Nn, 3 * Cc, Cc, Cc, Cc, 3 * Cc, 0, 0, 0);

    // 2. split + normalize
    normalize_kernel<<<Nn, 256>>>();

    // 3. sim_raw sums = vnflat @ vnflat^T : [2048,2048]
    sgemm_nt<<<dim3(Nn / BN, Nn / BM, 1), 256>>>(
        p_vnflat, p_vnflat, p_sim, Nn, Nn, Cc, Cc, Cc, Nn, 0, 0, 0);

    // 4. logits per head: qn_h @ kn_h^T (SCALE folded into qn), batched over heads
    sgemm_nt<<<dim3(Nn / BN, Nn / BM, Hh), 256>>>(
        p_q, p_k, p_attn, Nn, Nn, HD, HD, HD, Nn,
        (long long)Nn * HD, (long long)Nn * HD, (long long)Nn * Nn);

    // 5. masked scaled softmax in place
    softmax_kernel<<<dim3(Nn, Hh), 256>>>(cls);

    // 6. x = attn_h @ v_h : write into first half columns of x_out, batched
    sgemm_nt<<<dim3(HD / BN, Nn / BM, Hh), 256>>>(
        p_attn, p_vT, out, Nn, HD, Nn, Nn, Nn, 2 * Cc,
        (long long)Nn * Nn, (long long)HD * Nn, (long long)HD);

    // 7. x_ori = raw v into second half columns of x_out
    copy_v_kernel<<<(Nn * Cc / 4 + 255) / 256, 256>>>(out);

    // 8. sim_round2 into second output region
    simround2_kernel<<<Nn, 256>>>(out + (size_t)Nn * 2 * Cc);
}

// round 2
// speedup vs baseline: 1.1536x; 1.1536x over previous
#include <cuda_runtime.h>
#include <math.h>
#include <stdint.h>

// Problem constants
#define Nn   2048
#define Cc   1024
#define Hh   8
#define HD   128
#define SCALE_F 25.0f
#define SIM_THRESH 0.75f

// ---------------- scratch (device globals; no allocation allowed) ----------------
__device__ float g_qkv[Nn * 3 * Cc];            // [n][3C] raw qkv GEMM output
__device__ float g_q[Hh * Nn * HD];             // qn * SCALE, head-major [h][n][d]
__device__ float g_k[Hh * Nn * HD];             // kn, head-major
__device__ float g_vflat[Nn * Cc];              // raw v, flat [n][h*128+d]
__device__ float g_vnflat[Nn * Cc];             // per-head-normalized v, flat
__device__ float g_vT[Hh * HD * Nn];            // raw v transposed, [h][d][n]
__device__ float g_sim[Nn * Nn];                // sum_h vn.vn (before /8)
__device__ float g_attn[(size_t)Hh * Nn * Nn];  // logits -> softmaxed attn per head

// =====================================================================
// 3xTF32 tensor-core NT GEMM: C[M,N] = A[M,K] @ B[N,K]^T   (fp32 in/out)
// BM=BN=128, BK=16, 256 threads, 8 warps as 4(M)x2(N), warp tile 32x64.
// Shared tiles stored in mma-fragment-permuted layout (conflict-free LDS).
// hi/lo split (3xTF32) done in registers after LDS -> ~fp32 accuracy.
// =====================================================================

__device__ __forceinline__ void split_tf32(float v, uint32_t& hi, uint32_t& lo)
{
    uint32_t h;
    asm("cvt.rna.tf32.f32 %0, %1;" : "=r"(h) : "f"(v));
    hi = h;
    lo = __float_as_uint(v - __uint_as_float(h));
}

__device__ __forceinline__ void mma_tf32(float c[4], const uint32_t a[4],
                                         uint32_t b0, uint32_t b1)
{
    asm volatile(
        "mma.sync.aligned.m16n8k8.row.col.f32.tf32.tf32.f32 "
        "{%0,%1,%2,%3}, {%4,%5,%6,%7}, {%8,%9}, {%0,%1,%2,%3};"
        : "+f"(c[0]), "+f"(c[1]), "+f"(c[2]), "+f"(c[3])
        : "r"(a[0]), "r"(a[1]), "r"(a[2]), "r"(a[3]), "r"(b0), "r"(b1));
}

__global__ __launch_bounds__(256, 2) void tgemm_nt(
    const float* __restrict__ A, const float* __restrict__ B, float* __restrict__ C,
    int M, int N, int K, int lda, int ldb, int ldc,
    long long strideA, long long strideB, long long strideC)
{
    A += (long long)blockIdx.z * strideA;
    B += (long long)blockIdx.z * strideB;
    C += (long long)blockIdx.z * strideC;

    const int bm = blockIdx.y * 128;
    const int bn = blockIdx.x * 128;

    // permuted tiles: A 128x16 -> [chunk(=mBlock*2+kStep)][lane][reg(4)]
    //                 B 128x16 -> [chunk(=nBlock*2+kStep)][lane][reg(2)]
    __shared__ float As[2][2048];
    __shared__ float Bs[2][2048];

    const int tid  = threadIdx.x;
    const int lane = tid & 31;
    const int wid  = tid >> 5;
    const int wm   = wid >> 1;   // 0..3
    const int wn   = wid & 1;    // 0..1

    float cacc[2][8][4];
    #pragma unroll
    for (int mt = 0; mt < 2; mt++)
        #pragma unroll
        for (int nt = 0; nt < 8; nt++)
            #pragma unroll
            for (int r = 0; r < 4; r++) cacc[mt][nt][r] = 0.f;

    float4 ra[2], rb[2];

    const int nK = K / 16;

    // ---- stage 0 load ----
    #pragma unroll
    for (int t = 0; t < 2; t++) {
        int idx = tid + t * 256;
        int row = idx >> 2;
        int k4  = (idx & 3) * 4;
        ra[t] = *reinterpret_cast<const float4*>(&A[(long long)(bm + row) * lda + k4]);
        rb[t] = *reinterpret_cast<const float4*>(&B[(long long)(bn + row) * ldb + k4]);
    }
    // ---- store stage 0 ----
    #pragma unroll
    for (int t = 0; t < 2; t++) {
        int idx = tid + t * 256;
        int row = idx >> 2;
        int k4  = (idx & 3) * 4;
        {   // A scatter
            int mBlock = row >> 4, mIn = row & 15, kStep = k4 >> 3;
            int reg   = (mIn >> 3) + ((k4 & 4) >> 1);
            int base  = (((mBlock * 2 + kStep) * 32) + (mIn & 7) * 4) * 4 + reg;
            As[0][base + 0]  = ra[t].x;
            As[0][base + 4]  = ra[t].y;
            As[0][base + 8]  = ra[t].z;
            As[0][base + 12] = ra[t].w;
        }
        {   // B scatter
            int nBlock = row >> 3, nIn = row & 7, kStep = k4 >> 3;
            int reg   = (k4 & 4) >> 2;
            int base  = (((nBlock * 2 + kStep) * 32) + nIn * 4) * 2 + reg;
            Bs[0][base + 0] = rb[t].x;
            Bs[0][base + 2] = rb[t].y;
            Bs[0][base + 4] = rb[t].z;
            Bs[0][base + 6] = rb[t].w;
        }
    }
    __syncthreads();

    for (int it = 0; it < nK; ++it) {
        const int cur = it & 1;
        const bool hasNext = (it + 1 < nK);

        if (hasNext) {
            int k0 = (it + 1) * 16;
            #pragma unroll
            for (int t = 0; t < 2; t++) {
                int idx = tid + t * 256;
                int row = idx >> 2;
                int k4  = (idx & 3) * 4;
                ra[t] = *reinterpret_cast<const float4*>(&A[(long long)(bm + row) * lda + k0 + k4]);
                rb[t] = *reinterpret_cast<const float4*>(&B[(long long)(bn + row) * ldb + k0 + k4]);
            }
        }

        // ---- compute 2 k8-steps from buffer cur ----
        #pragma unroll
        for (int ks = 0; ks < 2; ks++) {
            uint32_t ahi[2][4], alo[2][4];
            #pragma unroll
            for (int mt = 0; mt < 2; mt++) {
                const float4 av = *reinterpret_cast<const float4*>(
                    &As[cur][(((wm * 2 + mt) * 2 + ks) * 32 + lane) * 4]);
                split_tf32(av.x, ahi[mt][0], alo[mt][0]);
                split_tf32(av.y, ahi[mt][1], alo[mt][1]);
                split_tf32(av.z, ahi[mt][2], alo[mt][2]);
                split_tf32(av.w, ahi[mt][3], alo[mt][3]);
            }
            #pragma unroll
            for (int nt = 0; nt < 8; nt++) {
                const float2 bv = *reinterpret_cast<const float2*>(
                    &Bs[cur][(((wn * 8 + nt) * 2 + ks) * 32 + lane) * 2]);
                uint32_t bhi0, blo0, bhi1, blo1;
                split_tf32(bv.x, bhi0, blo0);
                split_tf32(bv.y, bhi1, blo1);
                #pragma unroll
                for (int mt = 0; mt < 2; mt++) {
                    mma_tf32(cacc[mt][nt], ahi[mt], bhi0, bhi1);   // hi*hi
                    mma_tf32(cacc[mt][nt], alo[mt], bhi0, bhi1);   // lo*hi
                    mma_tf32(cacc[mt][nt], ahi[mt], blo0, blo1);   // hi*lo
                }
            }
        }

        if (hasNext) {
            const int nxt = 1 - cur;
            #pragma unroll
            for (int t = 0; t < 2; t++) {
                int idx = tid + t * 256;
                int row = idx >> 2;
                int k4  = (idx & 3) * 4;
                {
                    int mBlock = row >> 4, mIn = row & 15, kStep = k4 >> 3;
                    int reg  = (mIn >> 3) + ((k4 & 4) >> 1);
                    int base = (((mBlock * 2 + kStep) * 32) + (mIn & 7) * 4) * 4 + reg;
                    As[nxt][base + 0]  = ra[t].x;
                    As[nxt][base + 4]  = ra[t].y;
                    As[nxt][base + 8]  = ra[t].z;
                    As[nxt][base + 12] = ra[t].w;
                }
                {
                    int nBlock = row >> 3, nIn = row & 7, kStep = k4 >> 3;
                    int reg  = (k4 & 4) >> 2;
                    int base = (((nBlock * 2 + kStep) * 32) + nIn * 4) * 2 + reg;
                    Bs[nxt][base + 0] = rb[t].x;
                    Bs[nxt][base + 2] = rb[t].y;
                    Bs[nxt][base + 4] = rb[t].z;
                    Bs[nxt][base + 6] = rb[t].w;
                }
            }
        }
        __syncthreads();
    }

    // ---- epilogue ----
    #pragma unroll
    for (int mt = 0; mt < 2; mt++) {
        #pragma unroll
        for (int nt = 0; nt < 8; nt++) {
            int row0 = bm + wm * 32 + mt * 16 + (lane >> 2);
            int col  = bn + wn * 64 + nt * 8 + (lane & 3) * 2;
            float2 v0 = make_float2(cacc[mt][nt][0], cacc[mt][nt][1]);
            float2 v1 = make_float2(cacc[mt][nt][2], cacc[mt][nt][3]);
            *reinterpret_cast<float2*>(&C[(long long)row0 * ldc + col]) = v0;
            *reinterpret_cast<float2*>(&C[(long long)(row0 + 8) * ldc + col]) = v1;
        }
    }
}

// ---------------- normalize: split qkv, L2-normalize per head, build layouts ----------------
__global__ __launch_bounds__(256) void normalize_kernel()
{
    const int n = blockIdx.x;
    const int w = threadIdx.x >> 5;   // head
    const int lane = threadIdx.x & 31;
    const float* base = g_qkv + (long long)n * (3 * Cc);

    float qv[4], kv[4], vv[4];
    #pragma unroll
    for (int r = 0; r < 4; r++) {
        int d = lane + 32 * r;
        qv[r] = base[0 * Cc + w * HD + d];
        kv[r] = base[1 * Cc + w * HD + d];
        vv[r] = base[2 * Cc + w * HD + d];
    }
    float sq = 0.f, sk = 0.f, sv = 0.f;
    #pragma unroll
    for (int r = 0; r < 4; r++) { sq += qv[r] * qv[r]; sk += kv[r] * kv[r]; sv += vv[r] * vv[r]; }
    #pragma unroll
    for (int o = 16; o > 0; o >>= 1) {
        sq += __shfl_xor_sync(0xffffffffu, sq, o);
        sk += __shfl_xor_sync(0xffffffffu, sk, o);
        sv += __shfl_xor_sync(0xffffffffu, sv, o);
    }
    const float iq = SCALE_F / sqrtf(sq);
    const float ik = 1.0f / sqrtf(sk);
    const float iv = 1.0f / sqrtf(sv);

    #pragma unroll
    for (int r = 0; r < 4; r++) {
        int d = lane + 32 * r;
        g_q[(long long)w * Nn * HD + (long long)n * HD + d] = qv[r] * iq;
        g_k[(long long)w * Nn * HD + (long long)n * HD + d] = kv[r] * ik;
        g_vflat[(long long)n * Cc + w * HD + d]  = vv[r];
        g_vnflat[(long long)n * Cc + w * HD + d] = vv[r] * iv;
        g_vT[(long long)w * HD * Nn + (long long)d * Nn + n] = vv[r];
    }
}

// ---------------- block reduction helpers ----------------
__device__ __forceinline__ float blockMax(float v, float* sh)
{
    int tid = threadIdx.x;
    #pragma unroll
    for (int o = 16; o > 0; o >>= 1) v = fmaxf(v, __shfl_xor_sync(0xffffffffu, v, o));
    __syncthreads();
    if ((tid & 31) == 0) sh[tid >> 5] = v;
    __syncthreads();
    if (tid == 0) { float r = sh[0]; for (int i = 1; i < 8; i++) r = fmaxf(r, sh[i]); sh[8] = r; }
    __syncthreads();
    return sh[8];
}

__device__ __forceinline__ float blockSum(float v, float* sh)
{
    int tid = threadIdx.x;
    #pragma unroll
    for (int o = 16; o > 0; o >>= 1) v += __shfl_xor_sync(0xffffffffu, v, o);
    __syncthreads();
    if ((tid & 31) == 0) sh[tid >> 5] = v;
    __syncthreads();
    if (tid == 0) { float r = sh[0]; for (int i = 1; i < 8; i++) r += sh[i]; sh[8] = r; }
    __syncthreads();
    return sh[8];
}

// ---------------- per-row masked-scaled softmax over logits (in place) ----------------
__global__ __launch_bounds__(256) void softmax_kernel(const float* __restrict__ cls)
{
    const int i = blockIdx.x;
    const int h = blockIdx.y;
    const int tid = threadIdx.x;
    float* row = g_attn + (size_t)h * Nn * Nn + (size_t)i * Nn;
    const float thr = cls[i] - 0.1f;

    __shared__ float sh[16];
    float lv[8];
    float m = -1e30f;
    #pragma unroll
    for (int r = 0; r < 8; r++) {
        int j = tid + 256 * r;
        float cj = cls[j];
        float l = (cj > thr) ? row[j] * cj : 0.f;
        lv[r] = l;
        m = fmaxf(m, l);
    }
    m = blockMax(m, sh);
    float s = 0.f;
    #pragma unroll
    for (int r = 0; r < 8; r++) { lv[r] = expf(lv[r] - m); s += lv[r]; }
    s = blockSum(s, sh);
    const float iz = 1.0f / s;
    #pragma unroll
    for (int r = 0; r < 8; r++) row[tid + 256 * r] = lv[r] * iz;
}

// ---------------- copy raw v into second half of x_out ----------------
__global__ __launch_bounds__(256) void copy_v_kernel(float* __restrict__ out)
{
    int idx = blockIdx.x * blockDim.x + threadIdx.x;
    if (idx >= Nn * Cc / 4) return;
    int n = idx / (Cc / 4);
    int c4 = idx % (Cc / 4);
    float4 v = reinterpret_cast<const float4*>(g_vflat)[(size_t)n * (Cc / 4) + c4];
    reinterpret_cast<float4*>(out)[(size_t)n * (2 * Cc / 4) + (Cc / 4) + c4] = v;
}

// ---------------- sim_round2: head-avg attn -> softmax -> mask(sim>0.75) -> renorm ----------------
__global__ __launch_bounds__(256) void simround2_kernel(float* __restrict__ out_sim)
{
    const int i = blockIdx.x;
    const int tid = threadIdx.x;
    __shared__ float sh[16];

    float s[8];
    #pragma unroll
    for (int r = 0; r < 8; r++) {
        int j = tid + 256 * r;
        float acc = 0.f;
        #pragma unroll
        for (int h = 0; h < 8; h++)
            acc += g_attn[(size_t)h * Nn * Nn + (size_t)i * Nn + j];
        s[r] = acc * 0.125f;
    }
    float m = -1e30f;
    #pragma unroll
    for (int r = 0; r < 8; r++) m = fmaxf(m, s[r]);
    m = blockMax(m, sh);
    float z = 0.f;
    #pragma unroll
    for (int r = 0; r < 8; r++) { s[r] = expf(s[r] - m); z += s[r]; }
    z = blockSum(z, sh);
    const float iz = 1.0f / z;

    float msum = 0.f;
    #pragma unroll
    for (int r = 0; r < 8; r++) {
        int j = tid + 256 * r;
        float mk = (g_sim[(size_t)i * Nn + j] * 0.125f > SIM_THRESH) ? 1.f : 0.f;
        s[r] = mk * s[r] * iz;
        msum += s[r];
    }
    msum = blockSum(msum, sh);
    const float inv = 1.0f / msum;
    #pragma unroll
    for (int r = 0; r < 8; r++)
        out_sim[(size_t)i * Nn + tid + 256 * r] = s[r] * inv;
}

// ---------------- host launcher ----------------
extern "C" void kernel_launch(void* const* d_in, const int* in_sizes, int n_in,
                              void* d_out, int out_size)
{
    const float* x   = (const float*)d_in[0];  // [2048,1024]
    const float* cls = (const float*)d_in[1];  // [2048]
    const float* W   = (const float*)d_in[3];  // [3072,1024]
    float* out = (float*)d_out;                // x_out [2048,2048] then sim [2048,2048]

    float *p_qkv, *p_q, *p_k, *p_vnflat, *p_vT, *p_sim, *p_attn;
    cudaGetSymbolAddress((void**)&p_qkv, g_qkv);
    cudaGetSymbolAddress((void**)&p_q, g_q);
    cudaGetSymbolAddress((void**)&p_k, g_k);
    cudaGetSymbolAddress((void**)&p_vnflat, g_vnflat);
    cudaGetSymbolAddress((void**)&p_vT, g_vT);
    cudaGetSymbolAddress((void**)&p_sim, g_sim);
    cudaGetSymbolAddress((void**)&p_attn, g_attn);

    // 1. qkv = x @ W^T : [2048,3072]
    tgemm_nt<<<dim3(3 * Cc / 128, Nn / 128, 1), 256>>>(
        x, W, p_qkv, Nn, 3 * Cc, Cc, Cc, Cc, 3 * Cc, 0, 0, 0);

    // 2. split + normalize
    normalize_kernel<<<Nn, 256>>>();

    // 3. sim_raw sums = vnflat @ vnflat^T : [2048,2048]
    tgemm_nt<<<dim3(Nn / 128, Nn / 128, 1), 256>>>(
        p_vnflat, p_vnflat, p_sim, Nn, Nn, Cc, Cc, Cc, Nn, 0, 0, 0);

    // 4. logits per head: qn_h @ kn_h^T (SCALE folded into qn), batched over heads
    tgemm_nt<<<dim3(Nn / 128, Nn / 128, Hh), 256>>>(
        p_q, p_k, p_attn, Nn, Nn, HD, HD, HD, Nn,
        (long long)Nn * HD, (long long)Nn * HD, (long long)Nn * Nn);

    // 5. masked scaled softmax in place
    softmax_kernel<<<dim3(Nn, Hh), 256>>>(cls);

    // 6. x = attn_h @ v_h : into first half columns of x_out, batched
    tgemm_nt<<<dim3(HD / 128, Nn / 128, Hh), 256>>>(
        p_attn, p_vT, out, Nn, HD, Nn, Nn, Nn, 2 * Cc,
        (long long)Nn * Nn, (long long)HD * Nn, (long long)HD);

    // 7. x_ori = raw v into second half columns of x_out
    copy_v_kernel<<<(Nn * Cc / 4 + 255) / 256, 256>>>(out);

    // 8. sim_round2 into second output region
    simround2_kernel<<<Nn, 256>>>(out + (size_t)Nn * 2 * Cc);
}